// round 13
// baseline (speedup 1.0000x reference)
#include <cuda_runtime.h>

// harmolearn: 1024-channel LIF scan over 16368 steps, parallel-in-time via
// contraction warm-up chunks (w decays x0.5/step, mem x0.95/step).
// Identity: mean(B,axis=0)[j] at step t == colmean[t+j], so
// B_ram[c](t) = 16-window sliding sum of p[c,k] = x_pad[c,k]*colmean[k].
//
// Chunk geometry: 1023 body tiles split as 11 chunks x 24 tiles + 33 x 23
// (NCHUNK=44) -> 1408 warps, 9.5 blocks/SM, single wave at 136 regs.

#define CHN    1024
#define TLEN   16384
#define PADW   8
#define TP     (TLEN + 2 * PADW)   // 16400
#define NSTEPS (TLEN - 16)         // 16368
#define NCHUNK 44
#define WARM   320                 // 20 tiles: validated sub-ulp seam @ R12
#define WTILES (WARM / 16)         // 20

// padded past TP so speculative cp.async prefetches stay in-bounds (pad = 0)
__device__ __align__(16) float g_cm2[TP + 128];

// ---- cp.async helpers -------------------------------------------------------
__device__ __forceinline__ unsigned smem_u32(const void* p) {
    return (unsigned)__cvta_generic_to_shared(p);
}
__device__ __forceinline__ void cp_async16(unsigned dst, const void* src, int src_sz) {
    asm volatile("cp.async.cg.shared.global [%0], [%1], 16, %2;"
                 :: "r"(dst), "l"(src), "r"(src_sz));
}
__device__ __forceinline__ void cp_commit() {
    asm volatile("cp.async.commit_group;");
}
__device__ __forceinline__ void cp_wait1() {
    asm volatile("cp.async.wait_group 1;" ::: "memory");
}
__device__ __forceinline__ void cp_wait3() {
    asm volatile("cp.async.wait_group 3;" ::: "memory");
}
__device__ __forceinline__ void cp_wait0() {
    asm volatile("cp.async.wait_group 0;" ::: "memory");
}

// ---------------------------------------------------------------------------
// Kernel A: per-column channel mean * 0.5, strict ascending-c ADD order
// (bit-exact vs reference). Rows staged through a 5-deep cp.async smem ring.
// Block = 128 columns; stage = 16 rows x 128 cols = 8KB.
// ---------------------------------------------------------------------------
#define CM_DEPTH 5
__global__ void __launch_bounds__(128) colmean_kernel(const float* __restrict__ inp) {
    __shared__ __align__(16) float tile[CM_DEPTH][16][128];

    const int  tid  = threadIdx.x;
    const long cb   = (long)blockIdx.x * 128 - PADW;   // inp col of smem col 0
    const int  rr   = tid >> 5;                        // row sub-index 0..3
    const int  ccol = 4 * (tid & 31);                  // smem col group

    const long col  = cb + ccol;
    int szb = (col < 0) ? 0 : (int)((long)TLEN - col) * 4;
    szb = szb < 0 ? 0 : (szb > 16 ? 16 : szb);
    const float* srcBase = (szb > 0) ? (inp + col) : inp;

    // prefill stages 0..3
#pragma unroll
    for (int s = 0; s < CM_DEPTH - 1; ++s) {
#pragma unroll
        for (int q = 0; q < 4; ++q) {
            int row = 16 * s + rr + 4 * q;
            cp_async16(smem_u32(&tile[s][rr + 4 * q][ccol]),
                       srcBase + (size_t)row * TLEN, szb);
        }
        cp_commit();
    }

    const int tp      = blockIdx.x * 128 + tid;
    const bool active = (tp >= PADW) && (tp < TLEN + PADW);
    float s_acc = 0.0f;

    for (int s = 0; s < CHN / 16; ++s) {               // 64 stages
        cp_wait3();
        __syncthreads();
        if (s + CM_DEPTH - 1 < CHN / 16) {
            int sb = (s + CM_DEPTH - 1) % CM_DEPTH;
#pragma unroll
            for (int q = 0; q < 4; ++q) {
                int row = 16 * (s + CM_DEPTH - 1) + rr + 4 * q;
                cp_async16(smem_u32(&tile[sb][rr + 4 * q][ccol]),
                           srcBase + (size_t)row * TLEN, szb);
            }
            cp_commit();
        } else {
            cp_commit();                               // uniform group counting
        }
        if (active) {
            const int b = s % CM_DEPTH;
#pragma unroll
            for (int rI = 0; rI < 16; ++rI)
                s_acc = __fadd_rn(s_acc, tile[b][rI][tid]);  // strict ascending c
        }
    }
    if (tp < TP)
        g_cm2[tp] = active ? (s_acc * (1.0f / CHN)) * 0.5f : 0.0f;
}

// ---------------------------------------------------------------------------
// Kernel B: chunked scan. One warp per block = 32 consecutive channels x one
// time-chunk. x AND cm staged via cp.async two tiles ahead (3-buffer ring);
// pair-unrolled tiles; even-nt chunks run one standalone tile + role swap.
// Flush guard generalized: storeFrom may fall on either pair member.
// ---------------------------------------------------------------------------

#define STEPS(PA_, XA_, PB_, SB_)                                         \
  {                                                                       \
    float suf[16];                                                        \
    suf[15] = PA_[15];                                                    \
    _Pragma("unroll")                                                     \
    for (int i = 14; i >= 0; --i) suf[i] = __fadd_rn(PA_[i], suf[i + 1]); \
    float pre = 0.0f;                                                     \
    float4 sv;                                                            \
    _Pragma("unroll")                                                     \
    for (int i = 0; i < 16; ++i) {                                        \
      float d05 = (i == 0) ? suf[0] : __fadd_rn(suf[i], pre);             \
      w = fminf(fmaxf(__fmaf_rn(0.5f, w, d05), -1.0f), 3.0f);             \
      float bm = __fmul_rn(0.95f, mem);                                   \
      float wx = __fmul_rn(w, XA_[i]);                                    \
      mem = __fsub_rn(__fadd_rn(bm, wx), r);                              \
      r = (mem > 1.0f) ? 1.0f : 0.0f;                                     \
      ((float*)&sv)[i & 3] = r;                                           \
      if ((i & 3) == 3)                                                   \
        *reinterpret_cast<float4*>(&SB_[lane][i - 3]) = sv;               \
      pre = __fadd_rn(pre, PB_[i]);                                       \
    }                                                                     \
  }

#define CONSUME(XD_, PD_, BUF_)                                             \
  {                                                                         \
    const int bb_ = (BUF_);                                                 \
    float4 cm4[4];                                                          \
    _Pragma("unroll")                                                       \
    for (int q = 0; q < 4; ++q)                                             \
      cm4[q] = *reinterpret_cast<const float4*>(&cmx[bb_][4 * q]);          \
    _Pragma("unroll")                                                       \
    for (int q = 0; q < 4; ++q) {                                           \
      float4 xv = *reinterpret_cast<const float4*>(&sx[bb_][lane][4 * q]);  \
      XD_[4*q+0] = xv.x;  PD_[4*q+0] = __fmul_rn(xv.x, cm4[q].x);           \
      XD_[4*q+1] = xv.y;  PD_[4*q+1] = __fmul_rn(xv.y, cm4[q].y);           \
      XD_[4*q+2] = xv.z;  PD_[4*q+2] = __fmul_rn(xv.z, cm4[q].z);           \
      XD_[4*q+3] = xv.w;  PD_[4*q+3] = __fmul_rn(xv.w, cm4[q].w);           \
    }                                                                       \
  }

#define ISSUE(OFF_, BUF_)                                                   \
  {                                                                         \
    const int bb_ = (BUF_);                                                 \
    int szb_ = (TLEN - (idx + (OFF_))) * 4;                                 \
    szb_ = szb_ < 0 ? 0 : (szb_ > 16 ? 16 : szb_);                          \
    _Pragma("unroll")                                                       \
    for (int g = 0; g < 4; ++g) {                                           \
      const float* sp_ = szb_ ? (pSrc[g] + (OFF_)) : inp;                   \
      cp_async16(smem_u32(&sx[bb_][cg + 8 * g][4 * tq]), sp_, szb_);        \
    }                                                                       \
    if (lane < 4)                                                           \
      cp_async16(smem_u32(&cmx[bb_][4 * laneq]), pCm + (OFF_), 16);         \
    cp_commit();                                                            \
  }

#define FLUSH(SB_, OFF_)                                                     \
    _Pragma("unroll")                                                        \
    for (int g = 0; g < 4; ++g) {                                            \
      float4 v_ = *reinterpret_cast<const float4*>(&SB_[cg + 8 * g][4 * tq]);\
      *reinterpret_cast<float4*>(pOut[g] + (OFF_)) = v_;                     \
    }

__global__ void __launch_bounds__(32) scan_kernel(const float* __restrict__ inp,
                                                  float* __restrict__ out) {
    __shared__ __align__(16) float sx[3][32][20];   // x tiles ring
    __shared__ __align__(16) float cmx[3][16];      // cm tiles ring
    __shared__ __align__(16) float sb0[32][20];     // spikes (first pair member)
    __shared__ __align__(16) float sb1[32][20];     // spikes (second pair member)

    const int chunk = blockIdx.x >> 5;              // 0..43
    const int c0    = (blockIdx.x & 31) << 5;
    const int lane  = threadIdx.x;
    const float* row = inp + (size_t)(c0 + lane) * TLEN;

    // non-uniform bodies: chunks 0..10 have 24 tiles, 11..43 have 23 tiles
    const int S      = 23 * chunk + (chunk < 11 ? chunk : 11);  // start tile
    const int btiles = (chunk < 11) ? 24 : 23;
    const int tb = S << 4;
    int tw = tb - WARM;
    if (tw < 0) tw = 0;                              // chunk 0: exact init state
    const int wt        = (tb - tw) >> 4;            // 0 or 20
    const int nt        = btiles + wt;               // 24, 43, or 44
    const int storeFrom = wt;

    const int cg    = lane >> 2;
    const int tq    = lane & 3;
    const int laneq = lane & 3;

    // tail copy folded into last chunk
    if (chunk == NCHUNK - 1) {
#pragma unroll
        for (int q = 0; q < 4; ++q) {
            float4 v = *reinterpret_cast<const float4*>(row + NSTEPS + 4 * q);
            *reinterpret_cast<float4*>(out + (size_t)(c0 + lane) * TLEN + NSTEPS + 4 * q) = v;
        }
    }

    float w = 1.0f, mem = 0.0f, r = 0.0f;

    // ---- prologue: register windows 0 and 1 (scalar, one-time) ----
    float XA[16], PA[16], XB[16], PB[16];
#pragma unroll
    for (int j = 0; j < 16; ++j) {
        int k0 = tw + j;
        float x0 = (k0 >= PADW) ? __ldg(row + (k0 - PADW)) : 0.0f;
        XA[j] = x0;
        PA[j] = __fmul_rn(x0, __ldg(&g_cm2[k0]));
        int k1 = tw + 16 + j;
        float x1 = __ldg(row + (k1 - PADW));
        XB[j] = x1;
        PB[j] = __fmul_rn(x1, __ldg(&g_cm2[k1]));
    }

    // ---- prefill groups for windows 2 and 3 (ring buffers 0,1) ----
#pragma unroll
    for (int b = 0; b < 2; ++b) {
        int gb = tw + 24 + 16 * b;
#pragma unroll
        for (int g = 0; g < 4; ++g)
            cp_async16(smem_u32(&sx[b][cg + 8 * g][4 * tq]),
                       inp + (size_t)(c0 + cg + 8 * g) * TLEN + gb + 4 * tq, 16);
        if (lane < 4)
            cp_async16(smem_u32(&cmx[b][4 * laneq]), &g_cm2[tw + 32 + 16 * b + 4 * laneq], 16);
        cp_commit();
    }

    // ---- incrementing pointers (point at window k+4 data for tile k) ----
    const float* pSrc[4];
    float*       pOut[4];
#pragma unroll
    for (int g = 0; g < 4; ++g) {
        pSrc[g] = inp + (size_t)(c0 + cg + 8 * g) * TLEN + tw + 56 + 4 * tq;
        pOut[g] = out + (size_t)(c0 + cg + 8 * g) * TLEN + tw + 4 * tq;
    }
    const float* pCm = g_cm2 + tw + 64 + 4 * laneq;
    int idx = tw + 56 + 4 * tq;

    // ---- even-nt fixup: standalone tile 0 then role swap (nt=24,44 chunks) ----
    int kbase = 0;
    if ((nt & 1) == 0) {
        STEPS(PA, XA, PB, sb0);
        cp_wait1();
        __syncwarp();
        CONSUME(XA, PA, 0);              // window 2 -> XA/PA
        ISSUE(0, 2);                     // window 4 -> ring buffer 2
        if (0 >= storeFrom) { FLUSH(sb0, 0); }
#pragma unroll
        for (int g = 0; g < 4; ++g) { pSrc[g] += 16; pOut[g] += 16; }
        pCm += 16;
        idx += 16;
#pragma unroll
        for (int j = 0; j < 16; ++j) {
            float t0 = PA[j]; PA[j] = PB[j]; PB[j] = t0;
            float t1 = XA[j]; XA[j] = XB[j]; XB[j] = t1;
        }
        kbase = 1;
        __syncwarp();
    }

    // ---- pair-unrolled main loop (ring index b0 == k % 3) ----
    int b0 = kbase;
    const int pairs = (nt - kbase - 1) >> 1;
    for (int m = 0; m < pairs; ++m) {
        const int k = kbase + 2 * m;
        int b1 = b0 + 1; if (b1 == 3) b1 = 0;
        int b2 = b1 + 1; if (b2 == 3) b2 = 0;

        // tile k: pa=PA, x=XA, pb=PB
        STEPS(PA, XA, PB, sb0);
        cp_wait1();
        __syncwarp();
        CONSUME(XA, PA, b0);             // window k+2
        ISSUE(0, b2);                    // window k+4

        // tile k+1: pa=PB, x=XB, pb=PA(new)
        STEPS(PB, XB, PA, sb1);
        cp_wait1();
        __syncwarp();
        CONSUME(XB, PB, b1);             // window k+3
        ISSUE(16, b0);                   // window k+5

        // generalized store guard: storeFrom may equal k or k+1
        if (k >= storeFrom) {
            FLUSH(sb0, 0);
            FLUSH(sb1, 16);
        } else if (k + 1 == storeFrom) {
            FLUSH(sb1, 16);
        }

#pragma unroll
        for (int g = 0; g < 4; ++g) { pSrc[g] += 32; pOut[g] += 32; }
        pCm += 32;
        idx += 32;
        b0 = b2;
        __syncwarp();                    // protect sb0/sb1 reuse next pair
    }

    // ---- epilogue: last tile (nt-1, role A) ----
    STEPS(PA, XA, PB, sb0);
    __syncwarp();
    FLUSH(sb0, 0);
    cp_wait0();
}

extern "C" void kernel_launch(void* const* d_in, const int* in_sizes, int n_in,
                              void* d_out, int out_size) {
    const float* inp = (const float*)d_in[0];
    float* out = (float*)d_out;
    (void)in_sizes; (void)n_in; (void)out_size;

    colmean_kernel<<<(TP + 127) / 128, 128>>>(inp);
    scan_kernel<<<NCHUNK * 32, 32>>>(inp, out);
}

// round 17
// speedup vs baseline: 1.1463x; 1.1463x over previous
#include <cuda_runtime.h>

// harmolearn: 1024-channel LIF scan over 16368 steps, parallel-in-time via
// contraction warm-up chunks (w decays x0.5/step, mem x0.95/step).
// Identity: mean(B,axis=0)[j] at step t == colmean[t+j], so
// B_ram[c](t) = 16-window sliding sum of p[c,k] = x_pad[c,k]*colmean[k].
//
// R14: NCHUNK=33 (measured-best) + 4-tile-lead cp.async pipeline (5-buf ring).

#define CHN    1024
#define TLEN   16384
#define PADW   8
#define TP     (TLEN + 2 * PADW)   // 16400
#define NSTEPS (TLEN - 16)         // 16368
#define NCHUNK 33
#define BODY   496                 // 31 tiles;  33*496 = 16368
#define WARM   320                 // 20 tiles: validated sub-ulp seam @ R12
#define BTILES (BODY / 16)         // 31

// padded past TP so speculative cp.async prefetches stay in-bounds (pad = 0)
__device__ __align__(16) float g_cm2[TP + 128];

// ---- cp.async helpers -------------------------------------------------------
__device__ __forceinline__ unsigned smem_u32(const void* p) {
    return (unsigned)__cvta_generic_to_shared(p);
}
__device__ __forceinline__ void cp_async16(unsigned dst, const void* src, int src_sz) {
    asm volatile("cp.async.cg.shared.global [%0], [%1], 16, %2;"
                 :: "r"(dst), "l"(src), "r"(src_sz));
}
__device__ __forceinline__ void cp_commit() {
    asm volatile("cp.async.commit_group;");
}
__device__ __forceinline__ void cp_wait3() {
    asm volatile("cp.async.wait_group 3;" ::: "memory");
}
__device__ __forceinline__ void cp_wait0() {
    asm volatile("cp.async.wait_group 0;" ::: "memory");
}

// ---------------------------------------------------------------------------
// Kernel A: per-column channel mean * 0.5, strict ascending-c ADD order
// (bit-exact vs reference). Rows staged through a 5-deep cp.async smem ring.
// Block = 128 columns; stage = 16 rows x 128 cols = 8KB.
// ---------------------------------------------------------------------------
#define CM_DEPTH 5
__global__ void __launch_bounds__(128) colmean_kernel(const float* __restrict__ inp) {
    __shared__ __align__(16) float tile[CM_DEPTH][16][128];

    const int  tid  = threadIdx.x;
    const long cb   = (long)blockIdx.x * 128 - PADW;   // inp col of smem col 0
    const int  rr   = tid >> 5;                        // row sub-index 0..3
    const int  ccol = 4 * (tid & 31);                  // smem col group

    const long col  = cb + ccol;
    int szb = (col < 0) ? 0 : (int)((long)TLEN - col) * 4;
    szb = szb < 0 ? 0 : (szb > 16 ? 16 : szb);
    const float* srcBase = (szb > 0) ? (inp + col) : inp;

    // prefill stages 0..3
#pragma unroll
    for (int s = 0; s < CM_DEPTH - 1; ++s) {
#pragma unroll
        for (int q = 0; q < 4; ++q) {
            int row = 16 * s + rr + 4 * q;
            cp_async16(smem_u32(&tile[s][rr + 4 * q][ccol]),
                       srcBase + (size_t)row * TLEN, szb);
        }
        cp_commit();
    }

    const int tp      = blockIdx.x * 128 + tid;
    const bool active = (tp >= PADW) && (tp < TLEN + PADW);
    float s_acc = 0.0f;

    for (int s = 0; s < CHN / 16; ++s) {               // 64 stages
        cp_wait3();
        __syncthreads();
        if (s + CM_DEPTH - 1 < CHN / 16) {
            int sb = (s + CM_DEPTH - 1) % CM_DEPTH;
#pragma unroll
            for (int q = 0; q < 4; ++q) {
                int row = 16 * (s + CM_DEPTH - 1) + rr + 4 * q;
                cp_async16(smem_u32(&tile[sb][rr + 4 * q][ccol]),
                           srcBase + (size_t)row * TLEN, szb);
            }
            cp_commit();
        } else {
            cp_commit();                               // uniform group counting
        }
        if (active) {
            const int b = s % CM_DEPTH;
#pragma unroll
            for (int rI = 0; rI < 16; ++rI)
                s_acc = __fadd_rn(s_acc, tile[b][rI][tid]);  // strict ascending c
        }
    }
    if (tp < TP)
        g_cm2[tp] = active ? (s_acc * (1.0f / CHN)) * 0.5f : 0.0f;
}

// ---------------------------------------------------------------------------
// Kernel B: chunked scan. One warp per block = 32 consecutive channels x one
// time-chunk. x AND cm staged via cp.async FOUR tiles ahead (5-buffer ring,
// buffer = window % 5); pair-unrolled tiles; pointer-increment addressing.
// ---------------------------------------------------------------------------

#define STEPS(PA_, XA_, PB_, SB_)                                         \
  {                                                                       \
    float suf[16];                                                        \
    suf[15] = PA_[15];                                                    \
    _Pragma("unroll")                                                     \
    for (int i = 14; i >= 0; --i) suf[i] = __fadd_rn(PA_[i], suf[i + 1]); \
    float pre = 0.0f;                                                     \
    float4 sv;                                                            \
    _Pragma("unroll")                                                     \
    for (int i = 0; i < 16; ++i) {                                        \
      float d05 = (i == 0) ? suf[0] : __fadd_rn(suf[i], pre);             \
      w = fminf(fmaxf(__fmaf_rn(0.5f, w, d05), -1.0f), 3.0f);             \
      float bm = __fmul_rn(0.95f, mem);                                   \
      float wx = __fmul_rn(w, XA_[i]);                                    \
      mem = __fsub_rn(__fadd_rn(bm, wx), r);                              \
      r = (mem > 1.0f) ? 1.0f : 0.0f;                                     \
      ((float*)&sv)[i & 3] = r;                                           \
      if ((i & 3) == 3)                                                   \
        *reinterpret_cast<float4*>(&SB_[lane][i - 3]) = sv;               \
      pre = __fadd_rn(pre, PB_[i]);                                       \
    }                                                                     \
  }

#define CONSUME(XD_, PD_, BUF_)                                             \
  {                                                                         \
    const int bb_ = (BUF_);                                                 \
    float4 cm4[4];                                                          \
    _Pragma("unroll")                                                       \
    for (int q = 0; q < 4; ++q)                                             \
      cm4[q] = *reinterpret_cast<const float4*>(&cmx[bb_][4 * q]);          \
    _Pragma("unroll")                                                       \
    for (int q = 0; q < 4; ++q) {                                           \
      float4 xv = *reinterpret_cast<const float4*>(&sx[bb_][lane][4 * q]);  \
      XD_[4*q+0] = xv.x;  PD_[4*q+0] = __fmul_rn(xv.x, cm4[q].x);           \
      XD_[4*q+1] = xv.y;  PD_[4*q+1] = __fmul_rn(xv.y, cm4[q].y);           \
      XD_[4*q+2] = xv.z;  PD_[4*q+2] = __fmul_rn(xv.z, cm4[q].z);           \
      XD_[4*q+3] = xv.w;  PD_[4*q+3] = __fmul_rn(xv.w, cm4[q].w);           \
    }                                                                       \
  }

#define ISSUE(OFF_, BUF_)                                                   \
  {                                                                         \
    const int bb_ = (BUF_);                                                 \
    int szb_ = (TLEN - (idx + (OFF_))) * 4;                                 \
    szb_ = szb_ < 0 ? 0 : (szb_ > 16 ? 16 : szb_);                          \
    _Pragma("unroll")                                                       \
    for (int g = 0; g < 4; ++g) {                                           \
      const float* sp_ = szb_ ? (pSrc[g] + (OFF_)) : inp;                   \
      cp_async16(smem_u32(&sx[bb_][cg + 8 * g][4 * tq]), sp_, szb_);        \
    }                                                                       \
    if (lane < 4)                                                           \
      cp_async16(smem_u32(&cmx[bb_][4 * laneq]), pCm + (OFF_), 16);         \
    cp_commit();                                                            \
  }

#define FLUSH(SB_, OFF_)                                                     \
    _Pragma("unroll")                                                        \
    for (int g = 0; g < 4; ++g) {                                            \
      float4 v_ = *reinterpret_cast<const float4*>(&SB_[cg + 8 * g][4 * tq]);\
      *reinterpret_cast<float4*>(pOut[g] + (OFF_)) = v_;                     \
    }

__global__ void __launch_bounds__(32) scan_kernel(const float* __restrict__ inp,
                                                  float* __restrict__ out) {
    __shared__ __align__(16) float sx[5][32][20];   // x tiles ring (buf = win%5)
    __shared__ __align__(16) float cmx[5][16];      // cm tiles ring
    __shared__ __align__(16) float sb0[32][20];     // spikes (first pair member)
    __shared__ __align__(16) float sb1[32][20];     // spikes (second pair member)

    const int chunk = blockIdx.x >> 5;
    const int c0    = (blockIdx.x & 31) << 5;
    const int lane  = threadIdx.x;
    const float* row = inp + (size_t)(c0 + lane) * TLEN;

    const int tb = chunk * BODY;
    int tw = tb - WARM;
    if (tw < 0) tw = 0;                              // chunk 0: exact init state
    const int wt        = (tb - tw) >> 4;            // 0 or 20
    const int nt        = BTILES + wt;               // 31 or 51 (always odd)
    const int storeFrom = wt;

    const int cg    = lane >> 2;
    const int tq    = lane & 3;
    const int laneq = lane & 3;

    // tail copy folded into last chunk
    if (chunk == NCHUNK - 1) {
#pragma unroll
        for (int q = 0; q < 4; ++q) {
            float4 v = *reinterpret_cast<const float4*>(row + NSTEPS + 4 * q);
            *reinterpret_cast<float4*>(out + (size_t)(c0 + lane) * TLEN + NSTEPS + 4 * q) = v;
        }
    }

    float w = 1.0f, mem = 0.0f, r = 0.0f;

    // ---- prologue: register windows 0 and 1 (scalar, one-time) ----
    float XA[16], PA[16], XB[16], PB[16];
#pragma unroll
    for (int j = 0; j < 16; ++j) {
        int k0 = tw + j;
        float x0 = (k0 >= PADW) ? __ldg(row + (k0 - PADW)) : 0.0f;
        XA[j] = x0;
        PA[j] = __fmul_rn(x0, __ldg(&g_cm2[k0]));
        int k1 = tw + 16 + j;
        float x1 = __ldg(row + (k1 - PADW));
        XB[j] = x1;
        PB[j] = __fmul_rn(x1, __ldg(&g_cm2[k1]));
    }

    // ---- prefill windows 2..5 into ring buffers (win % 5): 4 groups ----
#pragma unroll
    for (int wi = 2; wi <= 5; ++wi) {
        const int bb = wi % 5;
        int gb = tw + 16 * wi - PADW;                // in-bounds: tw+24..tw+72
#pragma unroll
        for (int g = 0; g < 4; ++g)
            cp_async16(smem_u32(&sx[bb][cg + 8 * g][4 * tq]),
                       inp + (size_t)(c0 + cg + 8 * g) * TLEN + gb + 4 * tq, 16);
        if (lane < 4)
            cp_async16(smem_u32(&cmx[bb][4 * laneq]), &g_cm2[tw + 16 * wi + 4 * laneq], 16);
        cp_commit();
    }

    // ---- incrementing pointers (point at window k+6 data for tile k) ----
    const float* pSrc[4];
    float*       pOut[4];
#pragma unroll
    for (int g = 0; g < 4; ++g) {
        pSrc[g] = inp + (size_t)(c0 + cg + 8 * g) * TLEN + tw + 88 + 4 * tq;
        pOut[g] = out + (size_t)(c0 + cg + 8 * g) * TLEN + tw + 4 * tq;
    }
    const float* pCm = g_cm2 + tw + 96 + 4 * laneq;
    int idx = tw + 88 + 4 * tq;

    // ring cursor: bc = (k+2) % 5 = buffer consumed at tile k;
    // issue buffer for window k+6 = (bc+4) % 5
    int bc = 2;

    // ---- even-nt fixup: standalone tile 0 then role swap (safety; dead with
    //      current WARM/BODY since all nt are odd) ----
    int kbase = 0;
    if ((nt & 1) == 0) {
        STEPS(PA, XA, PB, sb0);
        cp_wait3();
        __syncwarp();
        CONSUME(XA, PA, bc);
        { int bi = bc + 4; if (bi >= 5) bi -= 5; ISSUE(0, bi); }
        if (0 >= storeFrom) { FLUSH(sb0, 0); }
#pragma unroll
        for (int g = 0; g < 4; ++g) { pSrc[g] += 16; pOut[g] += 16; }
        pCm += 16;
        idx += 16;
#pragma unroll
        for (int j = 0; j < 16; ++j) {
            float t0 = PA[j]; PA[j] = PB[j]; PB[j] = t0;
            float t1 = XA[j]; XA[j] = XB[j]; XB[j] = t1;
        }
        kbase = 1;
        if (++bc == 5) bc = 0;
        __syncwarp();
    }

    // ---- pair-unrolled main loop ----
    const int pairs = (nt - kbase - 1) >> 1;
    for (int m = 0; m < pairs; ++m) {
        const int k = kbase + 2 * m;
        int bc1 = bc + 1; if (bc1 >= 5) bc1 -= 5;    // consume buf for tile k+1
        int bi0 = bc + 4; if (bi0 >= 5) bi0 -= 5;    // issue buf window k+6
        int bi1 = bc;                                 // issue buf window k+7 == (bc1+4)%5

        // tile k: pa=PA, x=XA, pb=PB
        STEPS(PA, XA, PB, sb0);
        cp_wait3();
        __syncwarp();
        CONSUME(XA, PA, bc);             // window k+2
        ISSUE(0, bi0);                   // window k+6

        // tile k+1: pa=PB, x=XB, pb=PA(new)
        STEPS(PB, XB, PA, sb1);
        cp_wait3();
        __syncwarp();
        CONSUME(XB, PB, bc1);            // window k+3
        ISSUE(16, bi1);                  // window k+7

        // store guard: storeFrom may equal k or k+1 (parity-agnostic)
        if (k >= storeFrom) {
            FLUSH(sb0, 0);
            FLUSH(sb1, 16);
        } else if (k + 1 == storeFrom) {
            FLUSH(sb1, 16);
        }

#pragma unroll
        for (int g = 0; g < 4; ++g) { pSrc[g] += 32; pOut[g] += 32; }
        pCm += 32;
        idx += 32;
        bc = bc1 + 1; if (bc >= 5) bc -= 5;
        __syncwarp();                    // protect sb0/sb1 reuse next pair
    }

    // ---- epilogue: last tile (nt-1, role A) ----
    STEPS(PA, XA, PB, sb0);
    __syncwarp();
    FLUSH(sb0, 0);
    cp_wait0();
}

extern "C" void kernel_launch(void* const* d_in, const int* in_sizes, int n_in,
                              void* d_out, int out_size) {
    const float* inp = (const float*)d_in[0];
    float* out = (float*)d_out;
    (void)in_sizes; (void)n_in; (void)out_size;

    colmean_kernel<<<(TP + 127) / 128, 128>>>(inp);
    scan_kernel<<<NCHUNK * 32, 32>>>(inp, out);
}